// round 8
// baseline (speedup 1.0000x reference)
#include <cuda_runtime.h>

#define BB 4
#define HH 64
#define WW 64
#define LL 4096
#define DM 96
#define EE 192
#define NN 16
#define RR 6
#define KK 4
#define C38 38
#define NCH 64
#define CHL 64

// ---- scratch (static device globals — no allocation) ----
__device__ float g_xx[BB*EE*LL];          // pre-conv x (b,e,l)
__device__ float g_z [BB*LL*EE];          // silu(z)   (b,l,e)
__device__ float g_xc[BB*EE*LL];          // post-conv (b,e,l)
__device__ float g_xs[BB*2*LL*EE];        // scan-order u for dir 0/1 (b,j,p,e)
__device__ float g_dts[BB*KK*LL*8];       // (b,k,p,r) r<6, pad 8
__device__ float g_bc [BB*KK*LL*32];      // (b,k,p,{B0..15,C0..15})
__device__ float g_dt [BB*KK*LL*EE];      // softplus delta (b,k,p,e)
__device__ float g_sdt [BB*KK*NCH*EE];          // per-chunk sum dt
__device__ float g_hend[BB*KK*NCH*EE*NN];       // per-chunk h_end (zero init)
__device__ float g_h0  [BB*KK*NCH*EE*NN];       // per-chunk true h0
__device__ float g_yk[BB*KK*LL*EE];       // per-direction y (b,k,p,e)
__device__ float g_g [BB*LL*EE];          // post-LN gated (b,l,e)

__device__ __forceinline__ float siluf(float x){ return x / (1.f + __expf(-x)); }

// scan position p -> spatial index l (involution, also used as inverse)
__device__ __forceinline__ int mapf(int k, int p){
    if (k == 0) return p;
    if (k == 1) return ((p & 63) << 6) | (p >> 6);
    if (k == 2) return 4095 - p;
    int q = 4095 - p;
    return ((q & 63) << 6) | (q >> 6);
}

// ---------------- kernel 1: in_proj GEMM + split + silu(z) ----------------
__global__ void __launch_bounds__(256) k_inproj(const float* __restrict__ x,
                                                const float* __restrict__ w){
    __shared__ float As[64*48];
    __shared__ float Bs[48*68];
    int m0 = blockIdx.y * 64;
    int n0 = blockIdx.x * 64;
    int tid = threadIdx.x;
    int ty = tid >> 4, tx = tid & 15;
    float acc[4][4] = {};

    for (int kc = 0; kc < 96; kc += 48){
        for (int j = tid; j < 64*48; j += 256){
            int m = j / 48, kk = j % 48;
            As[j] = x[(m0 + m)*96 + kc + kk];
        }
        for (int j = tid; j < 64*48; j += 256){
            int nn = j / 48, kk = j % 48;
            Bs[kk*68 + nn] = w[(n0 + nn)*96 + kc + kk];
        }
        __syncthreads();
        #pragma unroll 8
        for (int kk = 0; kk < 48; kk++){
            float a[4], bv[4];
            #pragma unroll
            for (int i = 0; i < 4; i++) a[i] = As[(ty*4 + i)*48 + kk];
            #pragma unroll
            for (int j = 0; j < 4; j++) bv[j] = Bs[kk*68 + tx*4 + j];
            #pragma unroll
            for (int i = 0; i < 4; i++)
                #pragma unroll
                for (int j = 0; j < 4; j++)
                    acc[i][j] = fmaf(a[i], bv[j], acc[i][j]);
        }
        __syncthreads();
    }

    int mrow = m0 + ty*4;
    int b = mrow >> 12;
    int l = mrow & 4095;
    if (n0 < 192){
        #pragma unroll
        for (int j = 0; j < 4; j++){
            int n = n0 + tx*4 + j;
            float4 v = make_float4(acc[0][j], acc[1][j], acc[2][j], acc[3][j]);
            *(float4*)&g_xx[(b*EE + n)*LL + l] = v;
        }
    } else {
        #pragma unroll
        for (int i = 0; i < 4; i++){
            float4 v = make_float4(siluf(acc[i][0]), siluf(acc[i][1]),
                                   siluf(acc[i][2]), siluf(acc[i][3]));
            *(float4*)&g_z[(mrow + i)*EE + (n0 - 192) + tx*4] = v;
        }
    }
}

// ---------------- kernel 2: depthwise 3x3 conv + bias + silu ----------------
__global__ void k_conv(const float* __restrict__ cw, const float* __restrict__ cb){
    int be = blockIdx.y;
    int e = be % EE;
    int l = blockIdx.x * 256 + threadIdx.x;
    int h = l >> 6, w = l & 63;
    const float* in = &g_xx[be * LL];
    float acc = cb[e];
    #pragma unroll
    for (int dh = -1; dh <= 1; dh++){
        int hh = h + dh;
        if (hh < 0 || hh >= 64) continue;
        #pragma unroll
        for (int dw = -1; dw <= 1; dw++){
            int ww2 = w + dw;
            if (ww2 < 0 || ww2 >= 64) continue;
            acc = fmaf(in[hh*64 + ww2], cw[e*9 + (dh+1)*3 + (dw+1)], acc);
        }
    }
    g_xc[be*LL + l] = siluf(acc);
}

// ---------------- kernel 3: transpose xc -> scan-order u, dirs 0 and 1 ----------------
__global__ void __launch_bounds__(256) k_xs(){
    __shared__ float s[32][33];
    int l0 = blockIdx.x * 32;       // 32 l within one image row (h fixed)
    int e0 = blockIdx.y * 32;
    int b  = blockIdx.z;
    int tx = threadIdx.x & 31, ty = threadIdx.x >> 5;   // 32 x 8
    #pragma unroll
    for (int r = 0; r < 4; r++){
        int e = e0 + ty + r*8;
        s[ty + r*8][tx] = g_xc[((long)b*EE + e)*LL + l0 + tx];
    }
    __syncthreads();
    int h = l0 >> 6, w0 = l0 & 63;
    #pragma unroll
    for (int r = 0; r < 4; r++){
        int i = ty + r*8;
        int l = l0 + i;
        int p1 = ((w0 + i) << 6) | h;
        float v = s[tx][i];
        g_xs[((long)(b*2 + 0)*LL + l )*EE + e0 + tx] = v;
        g_xs[((long)(b*2 + 1)*LL + p1)*EE + e0 + tx] = v;
    }
}

// ---------------- kernel 4: x_dbl GEMM, written in scan order (split dts / B,C) ----------------
__global__ void __launch_bounds__(320) k_xdbl(const float* __restrict__ W){
    __shared__ float Xs[64*128];
    __shared__ float Ws[64*40];
    int l0 = blockIdx.x * 128;
    int k = blockIdx.y, b = blockIdx.z;
    int tid = threadIdx.x;
    int tc = tid / 32, tl = tid % 32;
    float acc[4][4] = {};

    for (int ec = 0; ec < 192; ec += 64){
        for (int j = tid; j < 64*128; j += 320){
            int e = j >> 7, l = j & 127;
            Xs[j] = g_xc[(b*EE + ec + e)*LL + l0 + l];
        }
        for (int j = tid; j < 40*64; j += 320){
            int c = j >> 6, e = j & 63;
            Ws[e*40 + c] = (c < C38) ? W[(k*C38 + c)*EE + ec + e] : 0.f;
        }
        __syncthreads();
        #pragma unroll 8
        for (int e = 0; e < 64; e++){
            float4 wv = *(const float4*)&Ws[e*40 + tc*4];
            float4 xv = *(const float4*)&Xs[e*128 + tl*4];
            float wf[4] = {wv.x, wv.y, wv.z, wv.w};
            float xf[4] = {xv.x, xv.y, xv.z, xv.w};
            #pragma unroll
            for (int ci = 0; ci < 4; ci++)
                #pragma unroll
                for (int li = 0; li < 4; li++)
                    acc[ci][li] = fmaf(wf[ci], xf[li], acc[ci][li]);
        }
        __syncthreads();
    }
    long bk = b*KK + k;
    #pragma unroll
    for (int li = 0; li < 4; li++){
        int l = l0 + tl*4 + li;
        int p = mapf(k, l);              // involution: spatial -> scan position
        #pragma unroll
        for (int j = 0; j < 4; j++){
            int c = tc*4 + j;
            float v = acc[j][li];
            if (c < 6)        g_dts[(bk*LL + p)*8  + c]     = v;
            else if (c < 38)  g_bc [(bk*LL + p)*32 + c - 6] = v;
        }
    }
}

// ---------------- kernel 5: delta = softplus(dts @ dtw^T + bias), (b,k,p,e) ----------------
__global__ void __launch_bounds__(192) k_dt(const float* __restrict__ dtw,
                                            const float* __restrict__ dtb){
    __shared__ float s[64*8];
    int pt = blockIdx.x * 64;
    int k = blockIdx.y, b = blockIdx.z;
    int e = threadIdx.x;
    long bk = b*KK + k;
    for (int j = e; j < 512; j += 192)
        s[j] = g_dts[(bk*LL + pt)*8 + j];
    float w[6];
    #pragma unroll
    for (int r = 0; r < 6; r++) w[r] = dtw[(k*EE + e)*RR + r];
    float bb = dtb[k*EE + e];
    __syncthreads();
    #pragma unroll 4
    for (int p = 0; p < 64; p++){
        float v = bb;
        #pragma unroll
        for (int r = 0; r < 6; r++) v = fmaf(w[r], s[p*8 + r], v);
        float d = (v > 15.f) ? v : __logf(1.f + __expf(v));
        g_dt[(bk*LL + pt + p)*EE + e] = d;
    }
}

// ---------------- kernel 6: scan pass A — per-chunk partial scan (h0 = 0) ----------------
__global__ void __launch_bounds__(192) k_scanA(const float* __restrict__ Alog){
    __shared__ float sB[CHL*16];
    int c = blockIdx.x, k = blockIdx.y, b = blockIdx.z;
    int e = threadIdx.x;
    long bk = b*KK + k;
    int p0 = c * CHL;
    for (int j = e; j < CHL*16; j += 192){
        int t = j >> 4, n = j & 15;
        sB[j] = g_bc[(bk*LL + p0 + t)*32 + n];
    }
    float An[16], h[16];
    #pragma unroll
    for (int n = 0; n < 16; n++){
        An[n] = -__expf(Alog[(k*EE + e)*NN + n]);
        h[n] = 0.f;
    }
    const float* dtp = &g_dt[(bk*LL + p0)*EE + e];
    int pp0  = (k < 2) ? p0 : (LL - 1 - p0);
    int pstp = (k < 2) ? 1 : -1;
    const float* up = &g_xs[((long)(b*2 + (k & 1))*LL + pp0)*EE + e];
    __syncthreads();

    float sdt = 0.f;
    float dt_nx = dtp[0];
    float u_nx  = up[0];
    #pragma unroll 2
    for (int t = 0; t < CHL; t++){
        float dt = dt_nx, u = u_nx;
        int t1 = (t + 1 < CHL) ? t + 1 : t;
        dt_nx = dtp[t1*EE];
        u_nx  = up [t1*pstp*EE];
        sdt += dt;
        float du = dt * u;
        #pragma unroll
        for (int n = 0; n < 16; n++){
            float dA = __expf(dt * An[n]);
            h[n] = fmaf(dA, h[n], du * sB[t*16 + n]);
        }
    }
    g_sdt[(bk*NCH + c)*EE + e] = sdt;
    float4* ho = (float4*)&g_hend[((bk*NCH + c)*EE + e)*16];
    #pragma unroll
    for (int q = 0; q < 4; q++)
        ho[q] = make_float4(h[q*4], h[q*4+1], h[q*4+2], h[q*4+3]);
}

// ---------------- kernel 7: scan pass B — sequential combine over chunks ----------------
__global__ void __launch_bounds__(256) k_scanB(const float* __restrict__ Alog){
    int gid = blockIdx.x * 256 + threadIdx.x;   // BB*KK*EE*NN lanes
    int n = gid & 15;
    int e = (gid >> 4) % EE;
    long bk = gid / (EE * NN);
    int k = (int)(bk & 3);
    float An = -__expf(Alog[(k*EE + e)*NN + n]);
    float h = 0.f;
    for (int c = 0; c < NCH; c++){
        long base = (bk*NCH + c)*EE + e;
        g_h0[base*16 + n] = h;
        float a = __expf(An * g_sdt[base]);
        h = fmaf(a, h, g_hend[base*16 + n]);
    }
}

// ---------------- kernel 8: scan pass C — rescan with true h0, emit y ----------------
__global__ void __launch_bounds__(192) k_scanC(const float* __restrict__ Alog,
                                               const float* __restrict__ Dsg){
    __shared__ float sBC[CHL*32];
    int c = blockIdx.x, k = blockIdx.y, b = blockIdx.z;
    int e = threadIdx.x;
    long bk = b*KK + k;
    int p0 = c * CHL;
    for (int j = e; j < CHL*32; j += 192)
        sBC[j] = g_bc[(bk*LL + p0)*32 + j];

    float An[16], h[16];
    const float4* hi = (const float4*)&g_h0[((bk*NCH + c)*EE + e)*16];
    #pragma unroll
    for (int q = 0; q < 4; q++){
        float4 v = hi[q];
        h[q*4] = v.x; h[q*4+1] = v.y; h[q*4+2] = v.z; h[q*4+3] = v.w;
    }
    #pragma unroll
    for (int n = 0; n < 16; n++)
        An[n] = -__expf(Alog[(k*EE + e)*NN + n]);
    float Dsv = Dsg[k*EE + e];

    const float* dtp = &g_dt[(bk*LL + p0)*EE + e];
    int pp0  = (k < 2) ? p0 : (LL - 1 - p0);
    int pstp = (k < 2) ? 1 : -1;
    const float* up = &g_xs[((long)(b*2 + (k & 1))*LL + pp0)*EE + e];
    float* yp = &g_yk[(bk*LL + p0)*EE + e];
    __syncthreads();

    float dt_nx = dtp[0];
    float u_nx  = up[0];
    #pragma unroll 2
    for (int t = 0; t < CHL; t++){
        float dt = dt_nx, u = u_nx;
        int t1 = (t + 1 < CHL) ? t + 1 : t;
        dt_nx = dtp[t1*EE];
        u_nx  = up [t1*pstp*EE];
        float du = dt * u;
        float y = Dsv * u;
        #pragma unroll
        for (int n = 0; n < 16; n++){
            float dA = __expf(dt * An[n]);
            h[n] = fmaf(dA, h[n], du * sBC[t*32 + n]);
            y = fmaf(h[n], sBC[t*32 + 16 + n], y);
        }
        yp[t*EE] = y;
    }
}

// ---------------- kernel 9: cross-merge + LayerNorm + gate ----------------
__global__ void __launch_bounds__(192) k_mergeln(const float* __restrict__ gamma,
                                                 const float* __restrict__ beta){
    int idx = blockIdx.x;            // b*L + l
    int b = idx >> 12, l = idx & 4095;
    int e = threadIdx.x;
    int hh = l >> 6, ww = l & 63;
    int pw = (ww << 6) | hh;
    long b4 = (long)b * 4;
    float v = g_yk[((b4 + 0)*LL + l          )*EE + e]
            + g_yk[((b4 + 1)*LL + pw         )*EE + e]
            + g_yk[((b4 + 2)*LL + (4095 - l) )*EE + e]
            + g_yk[((b4 + 3)*LL + (4095 - pw))*EE + e];
    float s = v, q = v*v;
    #pragma unroll
    for (int o = 16; o > 0; o >>= 1){
        s += __shfl_xor_sync(0xffffffffu, s, o);
        q += __shfl_xor_sync(0xffffffffu, q, o);
    }
    __shared__ float ss[6], sq[6];
    int wid = e >> 5, lane = e & 31;
    if (lane == 0){ ss[wid] = s; sq[wid] = q; }
    __syncthreads();
    if (e == 0){
        float S = 0.f, Q = 0.f;
        #pragma unroll
        for (int i = 0; i < 6; i++){ S += ss[i]; Q += sq[i]; }
        ss[0] = S; sq[0] = Q;
    }
    __syncthreads();
    float mu  = ss[0] * (1.f/192.f);
    float var = sq[0] * (1.f/192.f) - mu*mu;
    float r   = rsqrtf(var + 1e-5f);
    float yn  = (v - mu) * r * gamma[e] + beta[e];
    g_g[(long)idx*EE + e] = yn * g_z[(long)idx*EE + e];
}

// ---------------- kernel 10: out_proj GEMM ----------------
__global__ void __launch_bounds__(384) k_outproj(const float* __restrict__ Wo,
                                                 float* __restrict__ out){
    __shared__ float Gs [64*68];
    __shared__ float Ws2[64*100];
    int m0 = blockIdx.x * 64;
    int tid = threadIdx.x;
    int tn = tid / 16, tm = tid % 16;
    float acc[4][4] = {};

    for (int ec = 0; ec < 192; ec += 64){
        for (int j = tid; j < 64*64; j += 384){
            int ml = j >> 6, e = j & 63;
            Gs[e*68 + ml] = g_g[(long)(m0 + ml)*EE + ec + e];
        }
        for (int j = tid; j < 96*64; j += 384){
            int c2 = j >> 6, e = j & 63;
            Ws2[e*100 + c2] = Wo[c2*EE + ec + e];
        }
        __syncthreads();
        #pragma unroll 8
        for (int e = 0; e < 64; e++){
            float4 gv = *(const float4*)&Gs [e*68  + tm*4];
            float4 wv = *(const float4*)&Ws2[e*100 + tn*4];
            float gf[4] = {gv.x, gv.y, gv.z, gv.w};
            float wf[4] = {wv.x, wv.y, wv.z, wv.w};
            #pragma unroll
            for (int ci = 0; ci < 4; ci++)
                #pragma unroll
                for (int mi = 0; mi < 4; mi++)
                    acc[ci][mi] = fmaf(wf[ci], gf[mi], acc[ci][mi]);
        }
        __syncthreads();
    }
    #pragma unroll
    for (int mi = 0; mi < 4; mi++){
        int m = m0 + tm*4 + mi;
        float4 v = make_float4(acc[0][mi], acc[1][mi], acc[2][mi], acc[3][mi]);
        *(float4*)&out[m*96 + tn*4] = v;
    }
}

// ---------------- launch ----------------
extern "C" void kernel_launch(void* const* d_in, const int* in_sizes, int n_in,
                              void* d_out, int out_size){
    const float* x         = (const float*)d_in[0];
    const float* in_proj_w = (const float*)d_in[1];
    const float* conv_w    = (const float*)d_in[2];
    const float* conv_b    = (const float*)d_in[3];
    const float* x_proj_w  = (const float*)d_in[4];
    const float* dt_w      = (const float*)d_in[5];
    const float* dt_b      = (const float*)d_in[6];
    const float* A_logs    = (const float*)d_in[7];
    const float* Ds        = (const float*)d_in[8];
    const float* ln_g      = (const float*)d_in[9];
    const float* ln_b      = (const float*)d_in[10];
    const float* out_w     = (const float*)d_in[11];
    float* out = (float*)d_out;

    k_inproj <<< dim3(6, 256), 256 >>>(x, in_proj_w);
    k_conv   <<< dim3(LL/256, BB*EE), 256 >>>(conv_w, conv_b);
    k_xs     <<< dim3(128, 6, BB), 256 >>>();
    k_xdbl   <<< dim3(LL/128, KK, BB), 320 >>>(x_proj_w);
    k_dt     <<< dim3(LL/64, KK, BB), 192 >>>(dt_w, dt_b);
    k_scanA  <<< dim3(NCH, KK, BB), 192 >>>(A_logs);
    k_scanB  <<< (BB*KK*EE*NN)/256, 256 >>>(A_logs);
    k_scanC  <<< dim3(NCH, KK, BB), 192 >>>(A_logs, Ds);
    k_mergeln<<< BB*LL, 192 >>>(ln_g, ln_b);
    k_outproj<<< (BB*LL)/64, 384 >>>(out_w, out);

    (void)in_sizes; (void)n_in; (void)out_size;
}

// round 9
// speedup vs baseline: 1.0106x; 1.0106x over previous
#include <cuda_runtime.h>

#define BB 4
#define HH 64
#define WW 64
#define LL 4096
#define DM 96
#define EE 192
#define NN 16
#define RR 6
#define KK 4
#define C38 38
#define NCH 64
#define CHL 64

// ---- scratch (static device globals — no allocation) ----
__device__ float g_xx[BB*EE*LL];          // pre-conv x (b,e,l)
__device__ float g_z [BB*LL*EE];          // silu(z)   (b,l,e)
__device__ float g_xc[BB*EE*LL];          // post-conv (b,e,l)
__device__ float g_xs[BB*2*LL*EE];        // scan-order u for dir 0/1 (b,j,p,e)
__device__ float g_dts[BB*KK*LL*8];       // (b,k,p,r) r<6, pad 8
__device__ float g_bc [BB*KK*LL*32];      // (b,k,p,{B0..15,C0..15})
__device__ float g_dt [BB*KK*LL*EE];      // softplus delta (b,k,p,e)
__device__ float g_sdt [BB*KK*NCH*EE];          // per-chunk sum dt
__device__ float g_hend[BB*KK*NCH*EE*NN];       // per-chunk h_end (zero init)
__device__ float g_h0  [BB*KK*NCH*EE*NN];       // per-chunk true h0
__device__ float g_yk[BB*KK*LL*EE];       // per-direction y (b,k,p,e)
__device__ float g_g [BB*LL*EE];          // post-LN gated (b,l,e)

__device__ __forceinline__ float siluf(float x){ return x / (1.f + __expf(-x)); }

// scan position p -> spatial index l (involution, also used as inverse)
__device__ __forceinline__ int mapf(int k, int p){
    if (k == 0) return p;
    if (k == 1) return ((p & 63) << 6) | (p >> 6);
    if (k == 2) return 4095 - p;
    int q = 4095 - p;
    return ((q & 63) << 6) | (q >> 6);
}

// ---------------- kernel 1: in_proj GEMM + split + silu(z) ----------------
__global__ void __launch_bounds__(256) k_inproj(const float* __restrict__ x,
                                                const float* __restrict__ w){
    __shared__ float As[64*48];
    __shared__ float Bs[48*68];
    int m0 = blockIdx.y * 64;
    int n0 = blockIdx.x * 64;
    int tid = threadIdx.x;
    int ty = tid >> 4, tx = tid & 15;
    float acc[4][4] = {};

    for (int kc = 0; kc < 96; kc += 48){
        for (int j = tid; j < 64*48; j += 256){
            int m = j / 48, kk = j % 48;
            As[j] = x[(m0 + m)*96 + kc + kk];
        }
        for (int j = tid; j < 64*48; j += 256){
            int nn = j / 48, kk = j % 48;
            Bs[kk*68 + nn] = w[(n0 + nn)*96 + kc + kk];
        }
        __syncthreads();
        #pragma unroll 8
        for (int kk = 0; kk < 48; kk++){
            float a[4], bv[4];
            #pragma unroll
            for (int i = 0; i < 4; i++) a[i] = As[(ty*4 + i)*48 + kk];
            #pragma unroll
            for (int j = 0; j < 4; j++) bv[j] = Bs[kk*68 + tx*4 + j];
            #pragma unroll
            for (int i = 0; i < 4; i++)
                #pragma unroll
                for (int j = 0; j < 4; j++)
                    acc[i][j] = fmaf(a[i], bv[j], acc[i][j]);
        }
        __syncthreads();
    }

    int mrow = m0 + ty*4;
    int b = mrow >> 12;
    int l = mrow & 4095;
    if (n0 < 192){
        #pragma unroll
        for (int j = 0; j < 4; j++){
            int n = n0 + tx*4 + j;
            float4 v = make_float4(acc[0][j], acc[1][j], acc[2][j], acc[3][j]);
            *(float4*)&g_xx[(b*EE + n)*LL + l] = v;
        }
    } else {
        #pragma unroll
        for (int i = 0; i < 4; i++){
            float4 v = make_float4(siluf(acc[i][0]), siluf(acc[i][1]),
                                   siluf(acc[i][2]), siluf(acc[i][3]));
            *(float4*)&g_z[(mrow + i)*EE + (n0 - 192) + tx*4] = v;
        }
    }
}

// ---------------- kernel 2: depthwise 3x3 conv + bias + silu ----------------
__global__ void k_conv(const float* __restrict__ cw, const float* __restrict__ cb){
    int be = blockIdx.y;
    int e = be % EE;
    int l = blockIdx.x * 256 + threadIdx.x;
    int h = l >> 6, w = l & 63;
    const float* in = &g_xx[be * LL];
    float acc = cb[e];
    #pragma unroll
    for (int dh = -1; dh <= 1; dh++){
        int hh = h + dh;
        if (hh < 0 || hh >= 64) continue;
        #pragma unroll
        for (int dw = -1; dw <= 1; dw++){
            int ww2 = w + dw;
            if (ww2 < 0 || ww2 >= 64) continue;
            acc = fmaf(in[hh*64 + ww2], cw[e*9 + (dh+1)*3 + (dw+1)], acc);
        }
    }
    g_xc[be*LL + l] = siluf(acc);
}

// ---------------- kernel 3: transpose xc -> scan-order u, dirs 0 and 1 ----------------
__global__ void __launch_bounds__(256) k_xs(){
    __shared__ float s[32][33];
    int l0 = blockIdx.x * 32;       // 32 l within one image row (h fixed)
    int e0 = blockIdx.y * 32;
    int b  = blockIdx.z;
    int tx = threadIdx.x & 31, ty = threadIdx.x >> 5;   // 32 x 8
    #pragma unroll
    for (int r = 0; r < 4; r++){
        int e = e0 + ty + r*8;
        s[ty + r*8][tx] = g_xc[((long)b*EE + e)*LL + l0 + tx];
    }
    __syncthreads();
    int h = l0 >> 6, w0 = l0 & 63;
    #pragma unroll
    for (int r = 0; r < 4; r++){
        int i = ty + r*8;
        int l = l0 + i;
        int p1 = ((w0 + i) << 6) | h;
        float v = s[tx][i];
        g_xs[((long)(b*2 + 0)*LL + l )*EE + e0 + tx] = v;
        g_xs[((long)(b*2 + 1)*LL + p1)*EE + e0 + tx] = v;
    }
}

// ---------------- kernel 4: x_dbl GEMM, written in scan order (split dts / B,C) ----------------
__global__ void __launch_bounds__(320) k_xdbl(const float* __restrict__ W){
    __shared__ float Xs[64*128];
    __shared__ float Ws[64*40];
    int l0 = blockIdx.x * 128;
    int k = blockIdx.y, b = blockIdx.z;
    int tid = threadIdx.x;
    int tc = tid / 32, tl = tid % 32;
    float acc[4][4] = {};

    for (int ec = 0; ec < 192; ec += 64){
        for (int j = tid; j < 64*128; j += 320){
            int e = j >> 7, l = j & 127;
            Xs[j] = g_xc[(b*EE + ec + e)*LL + l0 + l];
        }
        for (int j = tid; j < 40*64; j += 320){
            int c = j >> 6, e = j & 63;
            Ws[e*40 + c] = (c < C38) ? W[(k*C38 + c)*EE + ec + e] : 0.f;
        }
        __syncthreads();
        #pragma unroll 8
        for (int e = 0; e < 64; e++){
            float4 wv = *(const float4*)&Ws[e*40 + tc*4];
            float4 xv = *(const float4*)&Xs[e*128 + tl*4];
            float wf[4] = {wv.x, wv.y, wv.z, wv.w};
            float xf[4] = {xv.x, xv.y, xv.z, xv.w};
            #pragma unroll
            for (int ci = 0; ci < 4; ci++)
                #pragma unroll
                for (int li = 0; li < 4; li++)
                    acc[ci][li] = fmaf(wf[ci], xf[li], acc[ci][li]);
        }
        __syncthreads();
    }
    long bk = b*KK + k;
    #pragma unroll
    for (int li = 0; li < 4; li++){
        int l = l0 + tl*4 + li;
        int p = mapf(k, l);              // involution: spatial -> scan position
        #pragma unroll
        for (int j = 0; j < 4; j++){
            int c = tc*4 + j;
            float v = acc[j][li];
            if (c < 6)        g_dts[(bk*LL + p)*8  + c]     = v;
            else if (c < 38)  g_bc [(bk*LL + p)*32 + c - 6] = v;
        }
    }
}

// ---------------- kernel 5: delta = softplus(dts @ dtw^T + bias), (b,k,p,e) ----------------
__global__ void __launch_bounds__(192) k_dt(const float* __restrict__ dtw,
                                            const float* __restrict__ dtb){
    __shared__ float s[64*8];
    int pt = blockIdx.x * 64;
    int k = blockIdx.y, b = blockIdx.z;
    int e = threadIdx.x;
    long bk = b*KK + k;
    for (int j = e; j < 512; j += 192)
        s[j] = g_dts[(bk*LL + pt)*8 + j];
    float w[6];
    #pragma unroll
    for (int r = 0; r < 6; r++) w[r] = dtw[(k*EE + e)*RR + r];
    float bb = dtb[k*EE + e];
    __syncthreads();
    #pragma unroll 4
    for (int p = 0; p < 64; p++){
        float v = bb;
        #pragma unroll
        for (int r = 0; r < 6; r++) v = fmaf(w[r], s[p*8 + r], v);
        float d = (v > 15.f) ? v : __logf(1.f + __expf(v));
        g_dt[(bk*LL + pt + p)*EE + e] = d;
    }
}

// ---------------- kernel 6: scan pass A — per-chunk partial scan (h0 = 0) ----------------
__global__ void __launch_bounds__(192) k_scanA(const float* __restrict__ Alog){
    __shared__ float sB[CHL*16];
    int c = blockIdx.x, k = blockIdx.y, b = blockIdx.z;
    int e = threadIdx.x;
    long bk = b*KK + k;
    int p0 = c * CHL;
    for (int j = e; j < CHL*16; j += 192){
        int t = j >> 4, n = j & 15;
        sB[j] = g_bc[(bk*LL + p0 + t)*32 + n];
    }
    float An[16], h[16];
    #pragma unroll
    for (int n = 0; n < 16; n++){
        An[n] = -__expf(Alog[(k*EE + e)*NN + n]);
        h[n] = 0.f;
    }
    const float* dtp = &g_dt[(bk*LL + p0)*EE + e];
    int pp0  = (k < 2) ? p0 : (LL - 1 - p0);
    int pstp = (k < 2) ? 1 : -1;
    const float* up = &g_xs[((long)(b*2 + (k & 1))*LL + pp0)*EE + e];
    __syncthreads();

    float sdt = 0.f;
    float dt_nx = dtp[0];
    float u_nx  = up[0];
    #pragma unroll 2
    for (int t = 0; t < CHL; t++){
        float dt = dt_nx, u = u_nx;
        int t1 = (t + 1 < CHL) ? t + 1 : t;
        dt_nx = dtp[t1*EE];
        u_nx  = up [t1*pstp*EE];
        sdt += dt;
        float du = dt * u;
        #pragma unroll
        for (int n = 0; n < 16; n++){
            float dA = __expf(dt * An[n]);
            h[n] = fmaf(dA, h[n], du * sB[t*16 + n]);
        }
    }
    g_sdt[(bk*NCH + c)*EE + e] = sdt;
    float4* ho = (float4*)&g_hend[((bk*NCH + c)*EE + e)*16];
    #pragma unroll
    for (int q = 0; q < 4; q++)
        ho[q] = make_float4(h[q*4], h[q*4+1], h[q*4+2], h[q*4+3]);
}

// ---------------- kernel 7: scan pass B — sequential combine over chunks ----------------
__global__ void __launch_bounds__(256) k_scanB(const float* __restrict__ Alog){
    int gid = blockIdx.x * 256 + threadIdx.x;   // BB*KK*EE*NN lanes
    int n = gid & 15;
    int e = (gid >> 4) % EE;
    long bk = gid / (EE * NN);
    int k = (int)(bk & 3);
    float An = -__expf(Alog[(k*EE + e)*NN + n]);
    float h = 0.f;
    for (int c = 0; c < NCH; c++){
        long base = (bk*NCH + c)*EE + e;
        g_h0[base*16 + n] = h;
        float a = __expf(An * g_sdt[base]);
        h = fmaf(a, h, g_hend[base*16 + n]);
    }
}

// ---------------- kernel 8: scan pass C — rescan with true h0, emit y ----------------
__global__ void __launch_bounds__(192) k_scanC(const float* __restrict__ Alog,
                                               const float* __restrict__ Dsg){
    __shared__ float sBC[CHL*32];
    int c = blockIdx.x, k = blockIdx.y, b = blockIdx.z;
    int e = threadIdx.x;
    long bk = b*KK + k;
    int p0 = c * CHL;
    for (int j = e; j < CHL*32; j += 192)
        sBC[j] = g_bc[(bk*LL + p0)*32 + j];

    float An[16], h[16];
    const float4* hi = (const float4*)&g_h0[((bk*NCH + c)*EE + e)*16];
    #pragma unroll
    for (int q = 0; q < 4; q++){
        float4 v = hi[q];
        h[q*4] = v.x; h[q*4+1] = v.y; h[q*4+2] = v.z; h[q*4+3] = v.w;
    }
    #pragma unroll
    for (int n = 0; n < 16; n++)
        An[n] = -__expf(Alog[(k*EE + e)*NN + n]);
    float Dsv = Dsg[k*EE + e];

    const float* dtp = &g_dt[(bk*LL + p0)*EE + e];
    int pp0  = (k < 2) ? p0 : (LL - 1 - p0);
    int pstp = (k < 2) ? 1 : -1;
    const float* up = &g_xs[((long)(b*2 + (k & 1))*LL + pp0)*EE + e];
    float* yp = &g_yk[(bk*LL + p0)*EE + e];
    __syncthreads();

    float dt_nx = dtp[0];
    float u_nx  = up[0];
    #pragma unroll 2
    for (int t = 0; t < CHL; t++){
        float dt = dt_nx, u = u_nx;
        int t1 = (t + 1 < CHL) ? t + 1 : t;
        dt_nx = dtp[t1*EE];
        u_nx  = up [t1*pstp*EE];
        float du = dt * u;
        float y = Dsv * u;
        #pragma unroll
        for (int n = 0; n < 16; n++){
            float dA = __expf(dt * An[n]);
            h[n] = fmaf(dA, h[n], du * sBC[t*32 + n]);
            y = fmaf(h[n], sBC[t*32 + 16 + n], y);
        }
        yp[t*EE] = y;
    }
}

// ---------------- kernel 9: cross-merge + LayerNorm + gate ----------------
__global__ void __launch_bounds__(192) k_mergeln(const float* __restrict__ gamma,
                                                 const float* __restrict__ beta){
    int idx = blockIdx.x;            // b*L + l
    int b = idx >> 12, l = idx & 4095;
    int e = threadIdx.x;
    int hh = l >> 6, ww = l & 63;
    int pw = (ww << 6) | hh;
    long b4 = (long)b * 4;
    float v = g_yk[((b4 + 0)*LL + l          )*EE + e]
            + g_yk[((b4 + 1)*LL + pw         )*EE + e]
            + g_yk[((b4 + 2)*LL + (4095 - l) )*EE + e]
            + g_yk[((b4 + 3)*LL + (4095 - pw))*EE + e];
    float s = v, q = v*v;
    #pragma unroll
    for (int o = 16; o > 0; o >>= 1){
        s += __shfl_xor_sync(0xffffffffu, s, o);
        q += __shfl_xor_sync(0xffffffffu, q, o);
    }
    __shared__ float ss[6], sq[6];
    int wid = e >> 5, lane = e & 31;
    if (lane == 0){ ss[wid] = s; sq[wid] = q; }
    __syncthreads();
    if (e == 0){
        float S = 0.f, Q = 0.f;
        #pragma unroll
        for (int i = 0; i < 6; i++){ S += ss[i]; Q += sq[i]; }
        ss[0] = S; sq[0] = Q;
    }
    __syncthreads();
    float mu  = ss[0] * (1.f/192.f);
    float var = sq[0] * (1.f/192.f) - mu*mu;
    float r   = rsqrtf(var + 1e-5f);
    float yn  = (v - mu) * r * gamma[e] + beta[e];
    g_g[(long)idx*EE + e] = yn * g_z[(long)idx*EE + e];
}

// ---------------- kernel 10: out_proj GEMM ----------------
__global__ void __launch_bounds__(384) k_outproj(const float* __restrict__ Wo,
                                                 float* __restrict__ out){
    __shared__ float Gs [64*68];
    __shared__ float Ws2[64*100];
    int m0 = blockIdx.x * 64;
    int tid = threadIdx.x;
    int tn = tid / 16, tm = tid % 16;
    float acc[4][4] = {};

    for (int ec = 0; ec < 192; ec += 64){
        for (int j = tid; j < 64*64; j += 384){
            int ml = j >> 6, e = j & 63;
            Gs[e*68 + ml] = g_g[(long)(m0 + ml)*EE + ec + e];
        }
        for (int j = tid; j < 96*64; j += 384){
            int c2 = j >> 6, e = j & 63;
            Ws2[e*100 + c2] = Wo[c2*EE + ec + e];
        }
        __syncthreads();
        #pragma unroll 8
        for (int e = 0; e < 64; e++){
            float4 gv = *(const float4*)&Gs [e*68  + tm*4];
            float4 wv = *(const float4*)&Ws2[e*100 + tn*4];
            float gf[4] = {gv.x, gv.y, gv.z, gv.w};
            float wf[4] = {wv.x, wv.y, wv.z, wv.w};
            #pragma unroll
            for (int ci = 0; ci < 4; ci++)
                #pragma unroll
                for (int mi = 0; mi < 4; mi++)
                    acc[ci][mi] = fmaf(wf[ci], gf[mi], acc[ci][mi]);
        }
        __syncthreads();
    }
    #pragma unroll
    for (int mi = 0; mi < 4; mi++){
        int m = m0 + tm*4 + mi;
        float4 v = make_float4(acc[0][mi], acc[1][mi], acc[2][mi], acc[3][mi]);
        *(float4*)&out[m*96 + tn*4] = v;
    }
}

// ---------------- launch ----------------
extern "C" void kernel_launch(void* const* d_in, const int* in_sizes, int n_in,
                              void* d_out, int out_size){
    const float* x         = (const float*)d_in[0];
    const float* in_proj_w = (const float*)d_in[1];
    const float* conv_w    = (const float*)d_in[2];
    const float* conv_b    = (const float*)d_in[3];
    const float* x_proj_w  = (const float*)d_in[4];
    const float* dt_w      = (const float*)d_in[5];
    const float* dt_b      = (const float*)d_in[6];
    const float* A_logs    = (const float*)d_in[7];
    const float* Ds        = (const float*)d_in[8];
    const float* ln_g      = (const float*)d_in[9];
    const float* ln_b      = (const float*)d_in[10];
    const float* out_w     = (const float*)d_in[11];
    float* out = (float*)d_out;

    k_inproj <<< dim3(6, 256), 256 >>>(x, in_proj_w);
    k_conv   <<< dim3(LL/256, BB*EE), 256 >>>(conv_w, conv_b);
    k_xs     <<< dim3(128, 6, BB), 256 >>>();
    k_xdbl   <<< dim3(LL/128, KK, BB), 320 >>>(x_proj_w);
    k_dt     <<< dim3(LL/64, KK, BB), 192 >>>(dt_w, dt_b);
    k_scanA  <<< dim3(NCH, KK, BB), 192 >>>(A_logs);
    k_scanB  <<< (BB*KK*EE*NN)/256, 256 >>>(A_logs);
    k_scanC  <<< dim3(NCH, KK, BB), 192 >>>(A_logs, Ds);
    k_mergeln<<< BB*LL, 192 >>>(ln_g, ln_b);
    k_outproj<<< (BB*LL)/64, 384 >>>(out_w, out);

    (void)in_sizes; (void)n_in; (void)out_size;
}